// round 10
// baseline (speedup 1.0000x reference)
#include <cuda_runtime.h>
#include <cuda_bf16.h>
#include <cstdint>

// Single kernel. Hot mini-table (6 rows, 3KB) in smem:
//   rows 0..4 : C[c] = W[65] + W[131] + W[133+c]   (diff chain, ~98.4% of pairs)
//   row  5    : W[132]                             (entity row, register-resident)
// Main loop is branchless (R5 shape): LDS jidx -> LDS.128 hot row -> pred entity
// add -> STG.128 streaming. Rare same-chain pairs (~1.6%) get a placeholder row
// in the main loop and are compacted into a list; Phase C recomputes them from W
// (3x LDG.128, L1-hot) and overwrites their output rows after __syncthreads().

__global__ void __launch_bounds__(256, 8)
rpe_main(const float* __restrict__ feats, const float* __restrict__ W,
         float* __restrict__ out, int n)
{
    __shared__ int jidx[1024];                   // (row*32) | ent<<30
    __shared__ __align__(16) float S[6 * 128];   // hot mini-table
    __shared__ int rare_list[1024];              // packed rare descriptors
    __shared__ int rare_cnt;

    const int tid = threadIdx.x;
    const int i   = blockIdx.x;

    if (tid == 0) rare_cnt = 0;

    // ---- Phase 0: build 6-row hot table ----
    for (int idx = tid; idx < 6 * 128; idx += 256) {
        const int r = idx >> 7;
        const int e = idx & 127;
        float v;
        if (r < 5) v = W[65 * 128 + e] + W[131 * 128 + e] + W[(133 + r) * 128 + e];
        else       v = W[132 * 128 + e];
        S[idx] = v;
    }

    // ---- Phase A: per-j packed index + rare compaction ----
    const float res_i  = feats[i * 10 + 0];
    const float tok_i  = feats[i * 10 + 1];
    const float asym_i = feats[i * 10 + 2];
    const float ent_i  = feats[i * 10 + 3];
    const float sym_i  = feats[i * 10 + 4];

    for (int j = tid; j < n; j += 256) {
        const float res_j  = feats[j * 10 + 0];
        const float tok_j  = feats[j * 10 + 1];
        const float asym_j = feats[j * 10 + 2];
        const float ent_j  = feats[j * 10 + 3];
        const float sym_j  = feats[j * 10 + 4];

        const int ent = (ent_i == ent_j) ? 1 : 0;

        if (asym_i == asym_j) {
            // rare: record (j | var<<10 | fix<<18 | ent<<26), placeholder row 0
            int var, fix;
            const int dres = (int)(res_i - res_j);
            if (dres != 0) { var = min(max(dres + 32, 0), 64);                    fix = 131; }
            else { const int dtok = (int)(tok_i - tok_j);
                   var = 66 + min(max(dtok + 32, 0), 64);                         fix = 32; }
            const int slot = atomicAdd(&rare_cnt, 1);
            rare_list[slot] = j | (var << 10) | (fix << 18) | (ent << 26);
            jidx[j] = 0;                                   // placeholder (overwritten in C)
        } else {
            const int row = min(max((int)(sym_i - sym_j) + 2, 0), 4);
            jidx[j] = (row * 32) | (ent << 30);
        }
    }
    __syncthreads();

    // ---- Phase B: branchless hot loop (R5 shape) ----
    const int e4    = tid & 31;                  // float4 lane within 128-dim row
    const int wid   = tid >> 5;
    const int warps = 8;
    const float4* __restrict__ S4 = (const float4*)S;

    const float4 went = S4[5 * 32 + e4];         // entity row in registers

    float* __restrict__ out_i = out + ((size_t)i * (size_t)n) * 128;

    int j = wid;
    for (; j + warps < n; j += 2 * warps) {
        const int j2 = j + warps;
        const int p0 = jidx[j];
        const int p1 = jidx[j2];
        float4 v0 = S4[(p0 & 0xFFFF) + e4];
        float4 v1 = S4[(p1 & 0xFFFF) + e4];
        if (p0 >> 30) { v0.x += went.x; v0.y += went.y; v0.z += went.z; v0.w += went.w; }
        if (p1 >> 30) { v1.x += went.x; v1.y += went.y; v1.z += went.z; v1.w += went.w; }
        __stcs((float4*)(out_i + (size_t)j  * 128) + e4, v0);
        __stcs((float4*)(out_i + (size_t)j2 * 128) + e4, v1);
    }
    for (; j < n; j += warps) {
        const int p = jidx[j];
        float4 v = S4[(p & 0xFFFF) + e4];
        if (p >> 30) { v.x += went.x; v.y += went.y; v.z += went.z; v.w += went.w; }
        __stcs((float4*)(out_i + (size_t)j * 128) + e4, v);
    }

    // ---- Phase C: overwrite rare rows (barrier orders the stores) ----
    __syncthreads();
    const int nr = rare_cnt;
    const float4* __restrict__ W4 = (const float4*)W;
    for (int k = wid; k < nr; k += warps) {
        const int d   = rare_list[k];
        const int jr  = d & 1023;
        const int var = (d >> 10) & 255;
        const int fix = (d >> 18) & 255;
        const float4 a = __ldg(&W4[var * 32 + e4]);
        const float4 b = __ldg(&W4[fix * 32 + e4]);
        const float4 c = __ldg(&W4[138 * 32 + e4]);
        float4 v;
        v.x = a.x + b.x + c.x;
        v.y = a.y + b.y + c.y;
        v.z = a.z + b.z + c.z;
        v.w = a.w + b.w + c.w;
        if ((d >> 26) & 1) { v.x += went.x; v.y += went.y; v.z += went.z; v.w += went.w; }
        __stcs((float4*)(out_i + (size_t)jr * 128) + e4, v);
    }
}

extern "C" void kernel_launch(void* const* d_in, const int* in_sizes, int n_in,
                              void* d_out, int out_size)
{
    const float* feats = (const float*)d_in[0];   // [1, n, 10] f32
    const float* W     = (const float*)d_in[1];   // [139, 128] f32
    float* out         = (float*)d_out;           // [1, n, n, 128] f32

    const int n = in_sizes[0] / 10;               // b == 1 (n == 1024)

    rpe_main<<<n, 256>>>(feats, W, out, n);
}

// round 11
// speedup vs baseline: 1.3234x; 1.3234x over previous
#include <cuda_runtime.h>
#include <cuda_bf16.h>
#include <cstdint>

// R5 structure (proven fastest) + 256-bit global accesses (sm_100+ v8.f32).
// Folded table in GLOBAL memory (i-independent, built once by a pre-kernel):
//   rows   0..4  : C[c] = W[65] + W[131] + W[133+c]   (diff chain, HOT: ~98.4%)
//   row    5     : W[132]                             (entity row)
//   rows   6..70 : A[r] = W[r] + W[131] + W[138]      (same chain, dres!=0)
//   rows  71..135: B[t] = W[32] + W[66+t] + W[138]    (same chain, dres==0)
// Phase B: warp = 2 rows x 16 lanes x 32B; one STG.256 per row-half.

#define TAB_ROWS 136

__device__ float g_table[TAB_ROWS * 128];

__global__ void build_table(const float* __restrict__ W)
{
    const int idx = blockIdx.x * blockDim.x + threadIdx.x;
    if (idx >= TAB_ROWS * 128) return;
    const int r = idx >> 7;
    const int e = idx & 127;
    float v;
    if (r < 5) {
        v = W[65 * 128 + e] + W[131 * 128 + e] + W[(133 + r) * 128 + e];
    } else if (r == 5) {
        v = W[132 * 128 + e];
    } else if (r < 71) {
        v = W[(r - 6) * 128 + e] + W[131 * 128 + e] + W[138 * 128 + e];
    } else {
        v = W[32 * 128 + e] + W[(66 + (r - 71)) * 128 + e] + W[138 * 128 + e];
    }
    g_table[idx] = v;
}

__device__ __forceinline__ void stg256(float* p, const float4& a, const float4& b)
{
    asm volatile("st.global.v8.f32 [%0], {%1,%2,%3,%4,%5,%6,%7,%8};"
                 :: "l"(p),
                    "f"(a.x), "f"(a.y), "f"(a.z), "f"(a.w),
                    "f"(b.x), "f"(b.y), "f"(b.z), "f"(b.w)
                 : "memory");
}

__global__ void __launch_bounds__(256, 7)
rpe_main(const float* __restrict__ feats, float* __restrict__ out, int n)
{
    __shared__ int jidx[1024];

    const int tid = threadIdx.x;
    const int i   = blockIdx.x;

    // ---- Phase A: per-j packed index (row | ent<<8) ----
    const float res_i  = feats[i * 10 + 0];
    const float tok_i  = feats[i * 10 + 1];
    const float asym_i = feats[i * 10 + 2];
    const float ent_i  = feats[i * 10 + 3];
    const float sym_i  = feats[i * 10 + 4];

    for (int j = tid; j < n; j += 256) {
        const float res_j  = feats[j * 10 + 0];
        const float tok_j  = feats[j * 10 + 1];
        const float asym_j = feats[j * 10 + 2];
        const float ent_j  = feats[j * 10 + 3];
        const float sym_j  = feats[j * 10 + 4];

        int row;
        if (asym_i == asym_j) {
            const int dres = (int)(res_i - res_j);
            if (dres != 0) {
                row = 6 + min(max(dres + 32, 0), 64);          // A table
            } else {
                const int dtok = (int)(tok_i - tok_j);
                row = 71 + min(max(dtok + 32, 0), 64);         // B table
            }
        } else {
            row = min(max((int)(sym_i - sym_j) + 2, 0), 4);    // C table (hot)
        }
        const int ent = (ent_i == ent_j) ? 1 : 0;
        jidx[j] = row | (ent << 8);
    }
    __syncthreads();

    // ---- Phase B: warp = 2 rows, 16 lanes x 32B each, STG.256 ----
    const int lane = tid & 31;
    const int e8   = lane & 15;          // 32B column within the 512B row
    const int pair = lane >> 4;          // which of the 2 rows this half-warp owns
    const int wid  = tid >> 5;           // 8 warps -> 16 rows per sweep

    const float4* __restrict__ T4 = (const float4*)g_table;

    // entity row (32B) in registers
    const float4 went_lo = __ldg(&T4[5 * 32 + 2 * e8]);
    const float4 went_hi = __ldg(&T4[5 * 32 + 2 * e8 + 1]);

    float* __restrict__ out_i = out + ((size_t)i * (size_t)n) * 128;

    for (int j0 = wid * 2; j0 < n; j0 += 16) {
        const int j = j0 + pair;
        const int p = jidx[j];                       // LDS (2 values/warp, bcast)
        const int base = (p & 255) * 32 + 2 * e8;

        float4 lo = __ldg(&T4[base]);
        float4 hi = __ldg(&T4[base + 1]);
        if (p >> 8) {
            lo.x += went_lo.x; lo.y += went_lo.y; lo.z += went_lo.z; lo.w += went_lo.w;
            hi.x += went_hi.x; hi.y += went_hi.y; hi.z += went_hi.z; hi.w += went_hi.w;
        }
        stg256(out_i + (size_t)j * 128 + e8 * 8, lo, hi);
    }
}

extern "C" void kernel_launch(void* const* d_in, const int* in_sizes, int n_in,
                              void* d_out, int out_size)
{
    const float* feats = (const float*)d_in[0];   // [1, n, 10] f32
    const float* W     = (const float*)d_in[1];   // [139, 128] f32
    float* out         = (float*)d_out;           // [1, n, n, 128] f32

    const int n = in_sizes[0] / 10;               // b == 1 (n == 1024)

    build_table<<<(TAB_ROWS * 128 + 255) / 256, 256>>>(W);
    rpe_main<<<n, 256>>>(feats, out, n);
}

// round 12
// speedup vs baseline: 1.3497x; 1.0199x over previous
#include <cuda_runtime.h>
#include <cuda_bf16.h>
#include <cstdint>

// R11 structure (proven fastest: global folded table + branchless STG.256 loop)
// + PDL: rpe_main launches while build_table is in flight; the table dependency
// is enforced by cudaGridDependencySynchronize() placed AFTER Phase A (which
// never touches the table).
//
// Folded table (i-independent):
//   rows   0..4  : C[c] = W[65] + W[131] + W[133+c]   (diff chain, HOT: ~98.4%)
//   row    5     : W[132]                             (entity row)
//   rows   6..70 : A[r] = W[r] + W[131] + W[138]      (same chain, dres!=0)
//   rows  71..135: B[t] = W[32] + W[66+t] + W[138]    (same chain, dres==0)

#define TAB_ROWS 136

__device__ float g_table[TAB_ROWS * 128];

__global__ void build_table(const float* __restrict__ W)
{
    const int idx = blockIdx.x * blockDim.x + threadIdx.x;
    if (idx < TAB_ROWS * 128) {
        const int r = idx >> 7;
        const int e = idx & 127;
        float v;
        if (r < 5) {
            v = W[65 * 128 + e] + W[131 * 128 + e] + W[(133 + r) * 128 + e];
        } else if (r == 5) {
            v = W[132 * 128 + e];
        } else if (r < 71) {
            v = W[(r - 6) * 128 + e] + W[131 * 128 + e] + W[138 * 128 + e];
        } else {
            v = W[32 * 128 + e] + W[(66 + (r - 71)) * 128 + e] + W[138 * 128 + e];
        }
        g_table[idx] = v;
    }
    // signal dependent kernel (memory made visible by PDL semantics)
    cudaTriggerProgrammaticLaunchCompletion();
}

__device__ __forceinline__ void stg256(float* p, const float4& a, const float4& b)
{
    asm volatile("st.global.v8.f32 [%0], {%1,%2,%3,%4,%5,%6,%7,%8};"
                 :: "l"(p),
                    "f"(a.x), "f"(a.y), "f"(a.z), "f"(a.w),
                    "f"(b.x), "f"(b.y), "f"(b.z), "f"(b.w)
                 : "memory");
}

__global__ void __launch_bounds__(256, 7)
rpe_main(const float* __restrict__ feats, float* __restrict__ out, int n)
{
    __shared__ int jidx[1024];

    const int tid = threadIdx.x;
    const int i   = blockIdx.x;

    // ---- Phase A: per-j packed index (row | ent<<8) — no table access ----
    const float res_i  = feats[i * 10 + 0];
    const float tok_i  = feats[i * 10 + 1];
    const float asym_i = feats[i * 10 + 2];
    const float ent_i  = feats[i * 10 + 3];
    const float sym_i  = feats[i * 10 + 4];

    for (int j = tid; j < n; j += 256) {
        const float res_j  = feats[j * 10 + 0];
        const float tok_j  = feats[j * 10 + 1];
        const float asym_j = feats[j * 10 + 2];
        const float ent_j  = feats[j * 10 + 3];
        const float sym_j  = feats[j * 10 + 4];

        int row;
        if (asym_i == asym_j) {
            const int dres = (int)(res_i - res_j);
            if (dres != 0) {
                row = 6 + min(max(dres + 32, 0), 64);          // A table
            } else {
                const int dtok = (int)(tok_i - tok_j);
                row = 71 + min(max(dtok + 32, 0), 64);         // B table
            }
        } else {
            row = min(max((int)(sym_i - sym_j) + 2, 0), 4);    // C table (hot)
        }
        const int ent = (ent_i == ent_j) ? 1 : 0;
        jidx[j] = row | (ent << 8);
    }

    // wait for build_table's writes to be visible (PDL dependency point)
    cudaGridDependencySynchronize();
    __syncthreads();

    // ---- Phase B: warp = 2 rows, 16 lanes x 32B each, STG.256 ----
    const int lane = tid & 31;
    const int e8   = lane & 15;          // 32B column within the 512B row
    const int pair = lane >> 4;          // which of the 2 rows this half-warp owns
    const int wid  = tid >> 5;           // 8 warps -> 16 rows per sweep

    const float4* __restrict__ T4 = (const float4*)g_table;

    // entity row (32B) in registers
    const float4 went_lo = __ldg(&T4[5 * 32 + 2 * e8]);
    const float4 went_hi = __ldg(&T4[5 * 32 + 2 * e8 + 1]);

    float* __restrict__ out_i = out + ((size_t)i * (size_t)n) * 128;

    for (int j0 = wid * 2; j0 < n; j0 += 16) {
        const int j = j0 + pair;
        const int p = jidx[j];                       // LDS (2 values/warp, bcast)
        const int base = (p & 255) * 32 + 2 * e8;

        float4 lo = __ldg(&T4[base]);
        float4 hi = __ldg(&T4[base + 1]);
        if (p >> 8) {
            lo.x += went_lo.x; lo.y += went_lo.y; lo.z += went_lo.z; lo.w += went_lo.w;
            hi.x += went_hi.x; hi.y += went_hi.y; hi.z += went_hi.z; hi.w += went_hi.w;
        }
        stg256(out_i + (size_t)j * 128 + e8 * 8, lo, hi);
    }
}

extern "C" void kernel_launch(void* const* d_in, const int* in_sizes, int n_in,
                              void* d_out, int out_size)
{
    const float* feats = (const float*)d_in[0];   // [1, n, 10] f32
    const float* W     = (const float*)d_in[1];   // [139, 128] f32
    float* out         = (float*)d_out;           // [1, n, n, 128] f32

    const int n = in_sizes[0] / 10;               // b == 1 (n == 1024)

    build_table<<<(TAB_ROWS * 128 + 255) / 256, 256>>>(W);

    // PDL launch: rpe_main may start while build_table is still running;
    // the device-side cudaGridDependencySynchronize() enforces the real dep.
    cudaLaunchConfig_t cfg = {};
    cfg.gridDim  = dim3(n, 1, 1);
    cfg.blockDim = dim3(256, 1, 1);
    cudaLaunchAttribute attr[1];
    attr[0].id = cudaLaunchAttributeProgrammaticStreamSerialization;
    attr[0].val.programmaticStreamSerializationAllowed = 1;
    cfg.attrs    = attr;
    cfg.numAttrs = 1;
    cudaLaunchKernelEx(&cfg, rpe_main, feats, out, n);
}